// round 15
// baseline (speedup 1.0000x reference)
#include <cuda_runtime.h>
#include <cuda_fp16.h>
#include <cstdint>

#define NA 10000
#define NE 320000
#define HD 128
#define NR 50
#define NL 6
#define NT 512
#define CUTR 5.0f
#define PI_F 3.14159265358979f

#define UMINF 0.0067379469990854670966f
#define INVTF ((1.0f - UMINF) / (float)(NT - 1))
#define SCALEF ((float)(NT - 1) / (1.0f - UMINF))

#define TM 80              // MMA tile rows
#define NBLKM 125          // 10000 / 80
#define MTHR 160           // 5 warps
#define PH 136             // padded halves per 128-col row (272B)
#define WSLOT 17408        // halves per padded 128x128 weight
#define BKT 32             // bucket capacity per node

typedef unsigned long long ull;

// ---------------- scratch ----------------
__device__ int    g_cnt[NA];
__device__ __align__(16) int2   g_bkt[(size_t)NA * BKT];
__device__ __align__(16) float  g_x[NA * HD];
__device__ __align__(16) __half g_msgh[NA * HD];
__device__ __align__(16) __half g_yh[NA * HD];
__device__ __align__(16) __half g_mh[NA * HD];
__device__ __align__(16) __half g_tblcf_h[(size_t)NL * NT * HD];
__device__ __align__(16) __half g_tbln_h[(size_t)NT * HD];
__device__ __align__(16) __half g_wt[(size_t)18 * WSLOT];
__device__ __align__(16) __half g_wc[(size_t)256 * PH];

__device__ __forceinline__ float silu_f(float x) { return x / (1.0f + __expf(-x)); }

__device__ __forceinline__ uint32_t smem_u32(const void* p) {
    uint32_t a;
    asm("{ .reg .u64 t; cvta.to.shared.u64 t, %1; cvt.u32.u64 %0, t; }" : "=r"(a) : "l"(p));
    return a;
}

// ================= MEGA SETUP =================
// [0,96) build_cf | [96,128) build_nbr | [128,146) wt | [146,148) wc |
// [148,348) embed | [348,973) geom+bucket
__global__ __launch_bounds__(512, 2)
void mega_setup(const int* __restrict__ ei, const float* __restrict__ pos,
                const int* __restrict__ z, const float* __restrict__ emb,
                const float* __restrict__ nemb,
                const float* __restrict__ means, const float* __restrict__ betas,
                const float* __restrict__ nprojW, const float* __restrict__ nprojB,
                const float* __restrict__ mlpW1, const float* __restrict__ mlpb1,
                const float* __restrict__ mlpW2, const float* __restrict__ mlpb2,
                const float* __restrict__ convW1, const float* __restrict__ convW2,
                const float* __restrict__ linW, const float* __restrict__ ncombW) {
    extern __shared__ float sh[];
    int b = blockIdx.x;
    int tid = threadIdx.x;
    if (b < 96) {
        int l = b >> 4;
        int blk = b & 15;
        float* sW1 = sh;
        float* sB1 = sW1 + NR * HD;
        float* sW2 = sB1 + HD;
        float* sB2 = sW2 + HD * HD;
        float* sMu = sB2 + HD;
        float* sBe = sMu + 64;
        float* sBuf = sBe + 64;
        const float* W1 = mlpW1 + (size_t)l * NR * HD;
        const float* W2 = mlpW2 + (size_t)l * HD * HD;
        for (int i = tid; i < NR * HD; i += 512) sW1[i] = W1[i];
        for (int i = tid; i < HD * HD; i += 512) sW2[i] = W2[i];
        if (tid < HD) { sB1[tid] = mlpb1[l * HD + tid]; sB2[tid] = mlpb2[l * HD + tid]; }
        if (tid < NR) { sMu[tid] = means[tid]; sBe[tid] = betas[tid]; }
        __syncthreads();
        int warp = tid >> 5, lane = tid & 31;
        float* sEA = sBuf + warp * 364;
        float* sH1 = sEA + 2 * NR;
        int t0 = (blk * 16 + warp) * 2;
        for (int i = lane; i < 2 * NR; i += 32) {
            int e = i / NR, r = i - e * NR;
            float u = UMINF + (float)(t0 + e) * INVTF;
            float d = -logf(u);
            float C = (d < CUTR) ? 0.5f * (cosf(PI_F * d / CUTR) + 1.f) : 0.f;
            float td = u - sMu[r];
            sEA[i] = C * expf(-sBe[r] * td * td);
        }
        __syncwarp();
        float4 acc[2];
        #pragma unroll
        for (int e = 0; e < 2; e++) acc[e] = make_float4(0.f, 0.f, 0.f, 0.f);
        #pragma unroll 2
        for (int r = 0; r < NR; r++) {
            float4 w = *(float4*)&sW1[r * HD + 4 * lane];
            #pragma unroll
            for (int e = 0; e < 2; e++) {
                float a = sEA[e * NR + r];
                acc[e].x = fmaf(a, w.x, acc[e].x);
                acc[e].y = fmaf(a, w.y, acc[e].y);
                acc[e].z = fmaf(a, w.z, acc[e].z);
                acc[e].w = fmaf(a, w.w, acc[e].w);
            }
        }
        float4 b1v = *(float4*)&sB1[4 * lane];
        #pragma unroll
        for (int e = 0; e < 2; e++) {
            int c0 = e * 132 + 4 * lane;
            sH1[c0 + 0] = silu_f(acc[e].x + b1v.x);
            sH1[c0 + 1] = silu_f(acc[e].y + b1v.y);
            sH1[c0 + 2] = silu_f(acc[e].z + b1v.z);
            sH1[c0 + 3] = silu_f(acc[e].w + b1v.w);
            acc[e] = make_float4(0.f, 0.f, 0.f, 0.f);
        }
        __syncwarp();
        #pragma unroll 2
        for (int r = 0; r < HD; r++) {
            float4 w = *(float4*)&sW2[r * HD + 4 * lane];
            #pragma unroll
            for (int e = 0; e < 2; e++) {
                float a = sH1[e * 132 + r];
                acc[e].x = fmaf(a, w.x, acc[e].x);
                acc[e].y = fmaf(a, w.y, acc[e].y);
                acc[e].z = fmaf(a, w.z, acc[e].z);
                acc[e].w = fmaf(a, w.w, acc[e].w);
            }
        }
        float4 b2v = *(float4*)&sB2[4 * lane];
        #pragma unroll
        for (int e = 0; e < 2; e++) {
            int t = t0 + e;
            float u = UMINF + (float)t * INVTF;
            float d = -logf(u);
            float C = (d < CUTR) ? 0.5f * (cosf(PI_F * d / CUTR) + 1.f) : 0.f;
            __half2* p = (__half2*)&g_tblcf_h[((size_t)l * NT + t) * HD + 4 * lane];
            p[0] = __floats2half2_rn((acc[e].x + b2v.x) * C, (acc[e].y + b2v.y) * C);
            p[1] = __floats2half2_rn((acc[e].z + b2v.z) * C, (acc[e].w + b2v.w) * C);
        }
    } else if (b < 128) {
        float* sW = sh;
        float* sB = sW + NR * HD;
        float* sMu = sB + HD;
        float* sBe = sMu + 64;
        float* sBuf = sBe + 64;
        for (int i = tid; i < NR * HD; i += 512) sW[i] = nprojW[i];
        if (tid < HD) sB[tid] = nprojB[tid];
        if (tid < NR) { sMu[tid] = means[tid]; sBe[tid] = betas[tid]; }
        __syncthreads();
        int warp = tid >> 5, lane = tid & 31;
        float* sEA = sBuf + warp * NR;
        int t = (b - 96) * 16 + warp;
        float u = UMINF + (float)t * INVTF;
        float d = -logf(u);
        float C = (d < CUTR) ? 0.5f * (cosf(PI_F * d / CUTR) + 1.f) : 0.f;
        for (int r = lane; r < NR; r += 32) {
            float td = u - sMu[r];
            sEA[r] = C * expf(-sBe[r] * td * td);
        }
        __syncwarp();
        float4 acc = make_float4(0.f, 0.f, 0.f, 0.f);
        #pragma unroll 2
        for (int r = 0; r < NR; r++) {
            float4 w = *(float4*)&sW[r * HD + 4 * lane];
            float a = sEA[r];
            acc.x = fmaf(a, w.x, acc.x);
            acc.y = fmaf(a, w.y, acc.y);
            acc.z = fmaf(a, w.z, acc.z);
            acc.w = fmaf(a, w.w, acc.w);
        }
        float4 bv = *(float4*)&sB[4 * lane];
        __half2* p = (__half2*)&g_tbln_h[(size_t)t * HD + 4 * lane];
        p[0] = __floats2half2_rn((acc.x + bv.x) * C, (acc.y + bv.y) * C);
        p[1] = __floats2half2_rn((acc.z + bv.z) * C, (acc.w + bv.w) * C);
    } else if (b < 146) {
        int mi = b - 128;
        const float* src;
        if (mi == 17) src = convW1;
        else {
            int l = mi / 3, j = mi % 3;
            src = (j == 0) ? convW2 + (size_t)l * 16384
                : (j == 1) ? linW + (size_t)l * 16384
                           : convW1 + (size_t)(l + 1) * 16384;
        }
        __half* dst = g_wt + (size_t)mi * WSLOT;
        for (int idx = tid; idx < 16384; idx += 512) {
            int k = idx >> 7, n = idx & 127;
            dst[k * PH + n] = __float2half(src[idx]);
        }
    } else if (b < 148) {
        int halfsel = b - 146;
        for (int i = tid; i < 16384; i += 512) {
            int idx = halfsel * 16384 + i;
            int k = idx >> 7, n = idx & 127;
            g_wc[k * PH + n] = __float2half(ncombW[idx]);
        }
    } else if (b < 348) {
        for (int idx = (b - 148) * 512 + tid; idx < NA * HD; idx += 200 * 512) {
            int i = idx >> 7, h = idx & 127;
            int zz = z[i];
            g_x[idx] = emb[(size_t)zz * HD + h];
            g_yh[idx] = __float2half(nemb[(size_t)zz * HD + h]);
        }
    } else {
        int e = (b - 348) * 512 + tid;
        if (e >= NE) return;
        int s = ei[e], d = ei[NE + e];
        float dx = pos[3 * s + 0] - pos[3 * d + 0];
        float dy = pos[3 * s + 1] - pos[3 * d + 1];
        float dz = pos[3 * s + 2] - pos[3 * d + 2];
        float d2 = dx * dx + dy * dy + dz * dz + 1e-12f;
        if (d2 < CUTR * CUTR) {
            float u = expf(-sqrtf(d2));
            int slot = atomicAdd(&g_cnt[d], 1);
            if (slot < BKT)
                g_bkt[(size_t)d * BKT + slot] = make_int2(s, __float_as_int(u));
        }
    }
}

// ---------------- scatter v5: half-warp per NODE (single wave) ----------------
__device__ __forceinline__ void edge_acc16(int j, int n, int hl, int self_mask,
        const __half* __restrict__ TBL, const __half* __restrict__ Y, float* acc) {
    int2 ed = __ldg(&g_bkt[j]);
    int s = ed.x;
    float u = __int_as_float(ed.y);
    float tf = fminf(fmaxf((u - UMINF) * SCALEF, 0.f), (float)(NT - 1));
    int ti = (int)tf;
    if (ti > NT - 2) ti = NT - 2;
    float fr = tf - (float)ti;
    float g = (self_mask && (s == n)) ? 0.f : 1.f;
    const uint4* r0 = (const uint4*)TBL + (size_t)ti * 16 + hl;
    uint4 h0 = __ldg(r0);
    uint4 h1 = __ldg(r0 + 16);
    uint4 hy = __ldg((const uint4*)Y + (size_t)s * 16 + hl);
    __half2 fr2 = __float2half2_rn(fr);
    unsigned A[4] = {h0.x, h0.y, h0.z, h0.w};
    unsigned B[4] = {h1.x, h1.y, h1.z, h1.w};
    unsigned Yv[4] = {hy.x, hy.y, hy.z, hy.w};
    #pragma unroll
    for (int q = 0; q < 4; q++) {
        __half2 a2 = *(__half2*)&A[q];
        __half2 b2 = *(__half2*)&B[q];
        __half2 y2 = *(__half2*)&Yv[q];
        __half2 w = __hfma2(fr2, __hsub2(b2, a2), a2);
        __half2 p = __hmul2(w, y2);
        float2 f = __half22float2(p);
        acc[2 * q]     = fmaf(f.x, g, acc[2 * q]);
        acc[2 * q + 1] = fmaf(f.y, g, acc[2 * q + 1]);
    }
}

__global__ __launch_bounds__(256)
void scatter_kernel(const __half* __restrict__ TBL, const __half* __restrict__ Y,
                    __half* __restrict__ M, int self_mask) {
    int warp = threadIdx.x >> 5, lane = threadIdx.x & 31;
    int hw = lane >> 4, hl = lane & 15;
    int n = blockIdx.x * 16 + warp * 2 + hw;   // one node per half-warp
    if (n >= NA) return;
    int cnt = min(__ldg(&g_cnt[n]), BKT);
    int beg = n * BKT, end = beg + cnt;
    float a0[8] = {0.f, 0.f, 0.f, 0.f, 0.f, 0.f, 0.f, 0.f};
    float a1[8] = {0.f, 0.f, 0.f, 0.f, 0.f, 0.f, 0.f, 0.f};
    int j = beg;
    for (; j + 1 < end; j += 2) {
        edge_acc16(j, n, hl, self_mask, TBL, Y, a0);
        edge_acc16(j + 1, n, hl, self_mask, TBL, Y, a1);
    }
    if (j < end) edge_acc16(j, n, hl, self_mask, TBL, Y, a0);
    #pragma unroll
    for (int q = 0; q < 8; q++) a0[q] += a1[q];
    __half2 h[4];
    #pragma unroll
    for (int q = 0; q < 4; q++) h[q] = __floats2half2_rn(a0[2 * q], a0[2 * q + 1]);
    uint4 st;
    st.x = *(unsigned*)&h[0]; st.y = *(unsigned*)&h[1];
    st.z = *(unsigned*)&h[2]; st.w = *(unsigned*)&h[3];
    ((uint4*)(M + (size_t)n * HD))[hl] = st;
}

// ================= mma.sync building blocks =================
__device__ __forceinline__ void mma_gemm(uint32_t aBase, int ksteps, uint32_t wBase, float* c) {
    #pragma unroll 2
    for (int k = 0; k < ksteps; k++) {
        uint32_t a0, a1, a2, a3;
        asm volatile("ldmatrix.sync.aligned.m8n8.x4.shared.b16 {%0,%1,%2,%3}, [%4];"
            : "=r"(a0), "=r"(a1), "=r"(a2), "=r"(a3) : "r"(aBase + k * 32));
        #pragma unroll
        for (int nbp = 0; nbp < 8; nbp++) {
            uint32_t b0, b1, b2r, b3;
            asm volatile("ldmatrix.sync.aligned.m8n8.x4.trans.shared.b16 {%0,%1,%2,%3}, [%4];"
                : "=r"(b0), "=r"(b1), "=r"(b2r), "=r"(b3)
                : "r"(wBase + k * (16 * 272) + nbp * 32));
            float* cp = c + nbp * 8;
            asm volatile("mma.sync.aligned.m16n8k16.row.col.f32.f16.f16.f32 "
                "{%0,%1,%2,%3}, {%4,%5,%6,%7}, {%8,%9}, {%0,%1,%2,%3};"
                : "+f"(cp[0]), "+f"(cp[1]), "+f"(cp[2]), "+f"(cp[3])
                : "r"(a0), "r"(a1), "r"(a2), "r"(a3), "r"(b0), "r"(b1));
            asm volatile("mma.sync.aligned.m16n8k16.row.col.f32.f16.f16.f32 "
                "{%0,%1,%2,%3}, {%4,%5,%6,%7}, {%8,%9}, {%0,%1,%2,%3};"
                : "+f"(cp[4]), "+f"(cp[5]), "+f"(cp[6]), "+f"(cp[7])
                : "r"(a0), "r"(a1), "r"(a2), "r"(a3), "r"(b2r), "r"(b3));
        }
    }
}

// ================= fused3 via mma.sync (TM=80 rows, 160 thr, grid 125) =================
__global__ __launch_bounds__(MTHR, 1)
void fused3_mma(const __half* __restrict__ M, const __half* __restrict__ WT,
                const float* __restrict__ b2, const float* __restrict__ bL,
                const float* __restrict__ X,
                float* __restrict__ xout, __half* __restrict__ yout, int has3) {
    extern __shared__ char smc[];
    uint32_t sb = smem_u32(smc);
    float* sBias = (float*)(smc + 126208);
    int tid = threadIdx.x, lane = tid & 31, warp = tid >> 5;
    int nw = has3 ? 3 : 2;
    {
        const uint4* ws = (const uint4*)WT;
        uint4* wd = (uint4*)(smc + 21760);
        for (int i = tid; i < nw * 2176; i += MTHR) wd[i] = ws[i];
    }
    if (tid < 128) { sBias[tid] = b2[tid]; sBias[128 + tid] = bL[tid]; }
    {
        int row = tid >> 1, sel = tid & 1;
        int node = min(blockIdx.x * TM + row, NA - 1);
        const uint4* src = (const uint4*)(M + (size_t)node * HD) + sel * 8;
        uint4* dst = (uint4*)(smc + row * 272 + sel * 128);
        #pragma unroll
        for (int i = 0; i < 8; i++) dst[i] = __ldg(src + i);
    }
    __syncthreads();

    int r0 = warp * 16;
    uint32_t aBase = sb + (r0 + (lane & 15)) * 272 + (lane >> 4) * 16;
    uint32_t bOff = ((lane & 7) + ((lane >> 3) & 1) * 8) * 272 + (lane >> 4) * 16;
    int cx = (lane & 3) * 2;
    int rtl = r0 + (lane >> 2);
    int nodeT = blockIdx.x * TM + rtl;
    int nodeB = nodeT + 8;
    int nT = min(nodeT, NA - 1), nB = min(nodeB, NA - 1);
    float c[64];

    #pragma unroll
    for (int nb = 0; nb < 16; nb++) {
        float bx0 = sBias[nb * 8 + cx], bx1 = sBias[nb * 8 + cx + 1];
        c[nb * 4 + 0] = bx0; c[nb * 4 + 1] = bx1; c[nb * 4 + 2] = bx0; c[nb * 4 + 3] = bx1;
    }
    mma_gemm(aBase, 8, sb + 21760 + bOff, c);
    __syncwarp();
    #pragma unroll
    for (int nb = 0; nb < 16; nb++) {
        int col = nb * 8 + cx;
        *(__half2*)(smc + rtl * 272 + col * 2) =
            __floats2half2_rn(silu_f(c[nb * 4 + 0]), silu_f(c[nb * 4 + 1]));
        *(__half2*)(smc + (rtl + 8) * 272 + col * 2) =
            __floats2half2_rn(silu_f(c[nb * 4 + 2]), silu_f(c[nb * 4 + 3]));
    }
    __syncwarp();

    #pragma unroll
    for (int nb = 0; nb < 16; nb++) {
        float bx0 = sBias[128 + nb * 8 + cx], bx1 = sBias[128 + nb * 8 + cx + 1];
        c[nb * 4 + 0] = bx0; c[nb * 4 + 1] = bx1; c[nb * 4 + 2] = bx0; c[nb * 4 + 3] = bx1;
    }
    mma_gemm(aBase, 8, sb + 21760 + 34816 + bOff, c);
    __syncwarp();
    #pragma unroll
    for (int nb = 0; nb < 16; nb++) {
        int col = nb * 8 + cx;
        float2 xT = *(const float2*)(X + (size_t)nT * HD + col);
        float2 xB = *(const float2*)(X + (size_t)nB * HD + col);
        float vT0 = c[nb * 4 + 0] + xT.x, vT1 = c[nb * 4 + 1] + xT.y;
        float vB0 = c[nb * 4 + 2] + xB.x, vB1 = c[nb * 4 + 3] + xB.y;
        if (nodeT < NA) *(float2*)(xout + (size_t)nodeT * HD + col) = make_float2(vT0, vT1);
        if (nodeB < NA) *(float2*)(xout + (size_t)nodeB * HD + col) = make_float2(vB0, vB1);
        if (has3) {
            *(__half2*)(smc + rtl * 272 + col * 2) = __floats2half2_rn(vT0, vT1);
            *(__half2*)(smc + (rtl + 8) * 272 + col * 2) = __floats2half2_rn(vB0, vB1);
        }
    }
    if (!has3) return;
    __syncwarp();

    #pragma unroll
    for (int i = 0; i < 64; i++) c[i] = 0.f;
    mma_gemm(aBase, 8, sb + 21760 + 69632 + bOff, c);
    #pragma unroll
    for (int nb = 0; nb < 16; nb++) {
        int col = nb * 8 + cx;
        if (nodeT < NA)
            *(__half2*)(yout + (size_t)nodeT * HD + col) =
                __floats2half2_rn(c[nb * 4 + 0], c[nb * 4 + 1]);
        if (nodeB < NA)
            *(__half2*)(yout + (size_t)nodeB * HD + col) =
                __floats2half2_rn(c[nb * 4 + 2], c[nb * 4 + 3]);
    }
}

// ================= comb via mma.sync (TM=80, 160 thr, grid 125) =================
__global__ __launch_bounds__(MTHR, 1)
void comb_mma(const __half* __restrict__ Wc, const __half* __restrict__ W1,
              const float* __restrict__ bc) {
    extern __shared__ char smc[];
    uint32_t sb = smem_u32(smc);
    float* sBias = (float*)(smc + 146688);
    int tid = threadIdx.x, lane = tid & 31, warp = tid >> 5;
    {
        const uint4* ws = (const uint4*)Wc;
        uint4* wd = (uint4*)(smc + 42240);
        for (int i = tid; i < 4352; i += MTHR) wd[i] = ws[i];
        const uint4* w1s = (const uint4*)W1;
        uint4* w1d = (uint4*)(smc + 111872);
        for (int i = tid; i < 2176; i += MTHR) w1d[i] = w1s[i];
    }
    if (tid < 128) sBias[tid] = bc[tid];
    {
        int row = tid >> 1, sel = tid & 1;
        int node = min(blockIdx.x * TM + row, NA - 1);
        uint4* dst = (uint4*)(smc + row * 528 + sel * 256);
        if (sel == 0) {
            const float4* src = (const float4*)(g_x + (size_t)node * HD);
            #pragma unroll
            for (int i = 0; i < 16; i++) {
                float4 v0 = __ldg(src + 2 * i), v1 = __ldg(src + 2 * i + 1);
                __half2 h0 = __floats2half2_rn(v0.x, v0.y);
                __half2 h1 = __floats2half2_rn(v0.z, v0.w);
                __half2 h2 = __floats2half2_rn(v1.x, v1.y);
                __half2 h3 = __floats2half2_rn(v1.z, v1.w);
                uint4 st;
                st.x = *(unsigned*)&h0; st.y = *(unsigned*)&h1;
                st.z = *(unsigned*)&h2; st.w = *(unsigned*)&h3;
                dst[i] = st;
            }
        } else {
            const uint4* src = (const uint4*)(g_msgh + (size_t)node * HD);
            #pragma unroll
            for (int i = 0; i < 16; i++) dst[i] = __ldg(src + i);
        }
    }
    __syncthreads();

    int r0 = warp * 16;
    uint32_t aBase = sb + (r0 + (lane & 15)) * 528 + (lane >> 4) * 16;
    uint32_t bOff = ((lane & 7) + ((lane >> 3) & 1) * 8) * 272 + (lane >> 4) * 16;
    int cx = (lane & 3) * 2;
    int rtl = r0 + (lane >> 2);
    int nodeT = blockIdx.x * TM + rtl;
    int nodeB = nodeT + 8;
    float c[64];

    #pragma unroll
    for (int nb = 0; nb < 16; nb++) {
        float bx0 = sBias[nb * 8 + cx], bx1 = sBias[nb * 8 + cx + 1];
        c[nb * 4 + 0] = bx0; c[nb * 4 + 1] = bx1; c[nb * 4 + 2] = bx0; c[nb * 4 + 3] = bx1;
    }
    mma_gemm(aBase, 16, sb + 42240 + bOff, c);
    __syncwarp();
    #pragma unroll
    for (int nb = 0; nb < 16; nb++) {
        int col = nb * 8 + cx;
        float vT0 = c[nb * 4 + 0], vT1 = c[nb * 4 + 1];
        float vB0 = c[nb * 4 + 2], vB1 = c[nb * 4 + 3];
        if (nodeT < NA) *(float2*)(g_x + (size_t)nodeT * HD + col) = make_float2(vT0, vT1);
        if (nodeB < NA) *(float2*)(g_x + (size_t)nodeB * HD + col) = make_float2(vB0, vB1);
        *(__half2*)(smc + rtl * 528 + col * 2) = __floats2half2_rn(vT0, vT1);
        *(__half2*)(smc + (rtl + 8) * 528 + col * 2) = __floats2half2_rn(vB0, vB1);
    }
    __syncwarp();

    #pragma unroll
    for (int i = 0; i < 64; i++) c[i] = 0.f;
    mma_gemm(aBase, 8, sb + 111872 + bOff, c);
    #pragma unroll
    for (int nb = 0; nb < 16; nb++) {
        int col = nb * 8 + cx;
        if (nodeT < NA)
            *(__half2*)(g_yh + (size_t)nodeT * HD + col) =
                __floats2half2_rn(c[nb * 4 + 0], c[nb * 4 + 1]);
        if (nodeB < NA)
            *(__half2*)(g_yh + (size_t)nodeB * HD + col) =
                __floats2half2_rn(c[nb * 4 + 2], c[nb * 4 + 3]);
    }
}

// ---------------- launcher ----------------
extern "C" void kernel_launch(void* const* d_in, const int* in_sizes, int n_in,
                              void* d_out, int out_size) {
    const int*   z      = (const int*)d_in[0];
    const float* pos    = (const float*)d_in[1];
    const int*   ei     = (const int*)d_in[3];
    const float* emb    = (const float*)d_in[4];
    const float* nemb   = (const float*)d_in[5];
    const float* nprojW = (const float*)d_in[6];
    const float* nprojB = (const float*)d_in[7];
    const float* ncombW = (const float*)d_in[8];
    const float* ncombB = (const float*)d_in[9];
    const float* means  = (const float*)d_in[10];
    const float* betas  = (const float*)d_in[11];
    const float* mlpW1  = (const float*)d_in[12];
    const float* mlpb1  = (const float*)d_in[13];
    const float* mlpW2  = (const float*)d_in[14];
    const float* mlpb2  = (const float*)d_in[15];
    const float* convW1 = (const float*)d_in[16];
    const float* convW2 = (const float*)d_in[17];
    const float* convb2 = (const float*)d_in[18];
    const float* linW   = (const float*)d_in[19];
    const float* linb   = (const float*)d_in[20];
    float* out = (float*)d_out;

    void *p_cnt, *p_x, *p_yh, *p_mh, *p_msgh, *p_tc, *p_tn, *p_wt, *p_wc;
    cudaGetSymbolAddress(&p_cnt, g_cnt);
    cudaGetSymbolAddress(&p_x, g_x);
    cudaGetSymbolAddress(&p_yh, g_yh);
    cudaGetSymbolAddress(&p_mh, g_mh);
    cudaGetSymbolAddress(&p_msgh, g_msgh);
    cudaGetSymbolAddress(&p_tc, g_tblcf_h);
    cudaGetSymbolAddress(&p_tn, g_tbln_h);
    cudaGetSymbolAddress(&p_wt, g_wt);
    cudaGetSymbolAddress(&p_wc, g_wc);
    float* px = (float*)p_x;
    __half* pyh = (__half*)p_yh;
    __half* pmh = (__half*)p_mh;
    __half* pmsgh = (__half*)p_msgh;
    __half* ptc = (__half*)p_tc;
    __half* ptn = (__half*)p_tn;
    __half* pwt = (__half*)p_wt;
    __half* pwc = (__half*)p_wc;

    size_t sh_mega = (size_t)28992 * sizeof(float);
    size_t sh_f3m  = 127232;
    size_t sh_cmm  = 147200;
    cudaFuncSetAttribute(mega_setup, cudaFuncAttributeMaxDynamicSharedMemorySize, (int)sh_mega);
    cudaFuncSetAttribute(fused3_mma, cudaFuncAttributeMaxDynamicSharedMemorySize, (int)sh_f3m);
    cudaFuncSetAttribute(comb_mma,   cudaFuncAttributeMaxDynamicSharedMemorySize, (int)sh_cmm);

    cudaMemsetAsync(p_cnt, 0, NA * sizeof(int));
    mega_setup<<<973, 512, sh_mega>>>(ei, pos, z, emb, nemb, means, betas,
                                      nprojW, nprojB, mlpW1, mlpb1, mlpW2, mlpb2,
                                      convW1, convW2, linW, ncombW);
    scatter_kernel<<<(NA + 15) / 16, 256>>>(ptn, pyh, pmsgh, 1);
    comb_mma<<<NBLKM, MTHR, sh_cmm>>>(pwc, pwt + (size_t)17 * WSLOT, ncombB);

    for (int l = 0; l < NL; l++) {
        scatter_kernel<<<(NA + 15) / 16, 256>>>(ptc + (size_t)l * NT * HD, pyh, pmh, 0);
        float* dest = (l == NL - 1) ? out : px;
        fused3_mma<<<NBLKM, MTHR, sh_f3m>>>(pmh, pwt + (size_t)(l * 3) * WSLOT,
                                            convb2 + (size_t)l * HD,
                                            linb + (size_t)l * HD,
                                            px, dest, pyh, (l < NL - 1) ? 1 : 0);
    }
}

// round 16
// speedup vs baseline: 1.0503x; 1.0503x over previous
#include <cuda_runtime.h>
#include <cuda_fp16.h>
#include <cstdint>

#define NA 10000
#define NE 320000
#define HD 128
#define NR 50
#define NL 6
#define NT 512
#define CUTR 5.0f
#define PI_F 3.14159265358979f

#define UMINF 0.0067379469990854670966f
#define INVTF ((1.0f - UMINF) / (float)(NT - 1))
#define SCALEF ((float)(NT - 1) / (1.0f - UMINF))

#define TM 80
#define NBLKM 125
#define MTHR 160
#define PH 136
#define WSLOT 17408
#define BKT 32

typedef unsigned long long ull;

// ---------------- scratch ----------------
__device__ int    g_cnt[NA];
__device__ __align__(16) int2   g_bkt[(size_t)NA * BKT];
__device__ __align__(16) float  g_x[NA * HD];
__device__ __align__(16) __half g_msgh[NA * HD];
__device__ __align__(16) __half g_yh[NA * HD];
__device__ __align__(16) __half g_mh[NA * HD];
__device__ __align__(16) __half g_tblcf_h[(size_t)NL * NT * HD];
__device__ __align__(16) __half g_tbln_h[(size_t)NT * HD];
__device__ __align__(16) __half g_wt[(size_t)18 * WSLOT];
__device__ __align__(16) __half g_wc[(size_t)256 * PH];

__device__ __forceinline__ float silu_f(float x) { return x / (1.0f + __expf(-x)); }

__device__ __forceinline__ uint32_t smem_u32(const void* p) {
    uint32_t a;
    asm("{ .reg .u64 t; cvta.to.shared.u64 t, %1; cvt.u32.u64 %0, t; }" : "=r"(a) : "l"(p));
    return a;
}

// ================= SETUP (heavy, smem): [0,96) build_cf | [96,128) build_nbr =================
__global__ __launch_bounds__(512, 1)
void setup_heavy(const float* __restrict__ means, const float* __restrict__ betas,
                 const float* __restrict__ nprojW, const float* __restrict__ nprojB,
                 const float* __restrict__ mlpW1, const float* __restrict__ mlpb1,
                 const float* __restrict__ mlpW2, const float* __restrict__ mlpb2) {
    extern __shared__ float sh[];
    int b = blockIdx.x;
    int tid = threadIdx.x;
    if (b < 96) {
        int l = b >> 4;
        int blk = b & 15;
        float* sW1 = sh;
        float* sB1 = sW1 + NR * HD;
        float* sW2 = sB1 + HD;
        float* sB2 = sW2 + HD * HD;
        float* sMu = sB2 + HD;
        float* sBe = sMu + 64;
        float* sBuf = sBe + 64;
        const float* W1 = mlpW1 + (size_t)l * NR * HD;
        const float* W2 = mlpW2 + (size_t)l * HD * HD;
        for (int i = tid; i < NR * HD; i += 512) sW1[i] = W1[i];
        for (int i = tid; i < HD * HD; i += 512) sW2[i] = W2[i];
        if (tid < HD) { sB1[tid] = mlpb1[l * HD + tid]; sB2[tid] = mlpb2[l * HD + tid]; }
        if (tid < NR) { sMu[tid] = means[tid]; sBe[tid] = betas[tid]; }
        __syncthreads();
        int warp = tid >> 5, lane = tid & 31;
        float* sEA = sBuf + warp * 364;
        float* sH1 = sEA + 2 * NR;
        int t0 = (blk * 16 + warp) * 2;
        for (int i = lane; i < 2 * NR; i += 32) {
            int e = i / NR, r = i - e * NR;
            float u = UMINF + (float)(t0 + e) * INVTF;
            float d = -logf(u);
            float C = (d < CUTR) ? 0.5f * (cosf(PI_F * d / CUTR) + 1.f) : 0.f;
            float td = u - sMu[r];
            sEA[i] = C * expf(-sBe[r] * td * td);
        }
        __syncwarp();
        float4 acc[2];
        #pragma unroll
        for (int e = 0; e < 2; e++) acc[e] = make_float4(0.f, 0.f, 0.f, 0.f);
        #pragma unroll 2
        for (int r = 0; r < NR; r++) {
            float4 w = *(float4*)&sW1[r * HD + 4 * lane];
            #pragma unroll
            for (int e = 0; e < 2; e++) {
                float a = sEA[e * NR + r];
                acc[e].x = fmaf(a, w.x, acc[e].x);
                acc[e].y = fmaf(a, w.y, acc[e].y);
                acc[e].z = fmaf(a, w.z, acc[e].z);
                acc[e].w = fmaf(a, w.w, acc[e].w);
            }
        }
        float4 b1v = *(float4*)&sB1[4 * lane];
        #pragma unroll
        for (int e = 0; e < 2; e++) {
            int c0 = e * 132 + 4 * lane;
            sH1[c0 + 0] = silu_f(acc[e].x + b1v.x);
            sH1[c0 + 1] = silu_f(acc[e].y + b1v.y);
            sH1[c0 + 2] = silu_f(acc[e].z + b1v.z);
            sH1[c0 + 3] = silu_f(acc[e].w + b1v.w);
            acc[e] = make_float4(0.f, 0.f, 0.f, 0.f);
        }
        __syncwarp();
        #pragma unroll 2
        for (int r = 0; r < HD; r++) {
            float4 w = *(float4*)&sW2[r * HD + 4 * lane];
            #pragma unroll
            for (int e = 0; e < 2; e++) {
                float a = sH1[e * 132 + r];
                acc[e].x = fmaf(a, w.x, acc[e].x);
                acc[e].y = fmaf(a, w.y, acc[e].y);
                acc[e].z = fmaf(a, w.z, acc[e].z);
                acc[e].w = fmaf(a, w.w, acc[e].w);
            }
        }
        float4 b2v = *(float4*)&sB2[4 * lane];
        #pragma unroll
        for (int e = 0; e < 2; e++) {
            int t = t0 + e;
            float u = UMINF + (float)t * INVTF;
            float d = -logf(u);
            float C = (d < CUTR) ? 0.5f * (cosf(PI_F * d / CUTR) + 1.f) : 0.f;
            __half2* p = (__half2*)&g_tblcf_h[((size_t)l * NT + t) * HD + 4 * lane];
            p[0] = __floats2half2_rn((acc[e].x + b2v.x) * C, (acc[e].y + b2v.y) * C);
            p[1] = __floats2half2_rn((acc[e].z + b2v.z) * C, (acc[e].w + b2v.w) * C);
        }
    } else {
        float* sW = sh;
        float* sB = sW + NR * HD;
        float* sMu = sB + HD;
        float* sBe = sMu + 64;
        float* sBuf = sBe + 64;
        for (int i = tid; i < NR * HD; i += 512) sW[i] = nprojW[i];
        if (tid < HD) sB[tid] = nprojB[tid];
        if (tid < NR) { sMu[tid] = means[tid]; sBe[tid] = betas[tid]; }
        __syncthreads();
        int warp = tid >> 5, lane = tid & 31;
        float* sEA = sBuf + warp * NR;
        int t = (b - 96) * 16 + warp;
        float u = UMINF + (float)t * INVTF;
        float d = -logf(u);
        float C = (d < CUTR) ? 0.5f * (cosf(PI_F * d / CUTR) + 1.f) : 0.f;
        for (int r = lane; r < NR; r += 32) {
            float td = u - sMu[r];
            sEA[r] = C * expf(-sBe[r] * td * td);
        }
        __syncwarp();
        float4 acc = make_float4(0.f, 0.f, 0.f, 0.f);
        #pragma unroll 2
        for (int r = 0; r < NR; r++) {
            float4 w = *(float4*)&sW[r * HD + 4 * lane];
            float a = sEA[r];
            acc.x = fmaf(a, w.x, acc.x);
            acc.y = fmaf(a, w.y, acc.y);
            acc.z = fmaf(a, w.z, acc.z);
            acc.w = fmaf(a, w.w, acc.w);
        }
        float4 bv = *(float4*)&sB[4 * lane];
        __half2* p = (__half2*)&g_tbln_h[(size_t)t * HD + 4 * lane];
        p[0] = __floats2half2_rn((acc.x + bv.x) * C, (acc.y + bv.y) * C);
        p[1] = __floats2half2_rn((acc.z + bv.z) * C, (acc.w + bv.w) * C);
    }
}

// ===== SETUP (light, no smem): [0,18) wt | [18,20) wc | [20,220) embed | [220,845) geom =====
__global__ __launch_bounds__(512)
void setup_light(const int* __restrict__ ei, const float* __restrict__ pos,
                 const int* __restrict__ z, const float* __restrict__ emb,
                 const float* __restrict__ nemb,
                 const float* __restrict__ convW1, const float* __restrict__ convW2,
                 const float* __restrict__ linW, const float* __restrict__ ncombW) {
    int b = blockIdx.x;
    int tid = threadIdx.x;
    if (b < 18) {
        int mi = b;
        const float* src;
        if (mi == 17) src = convW1;
        else {
            int l = mi / 3, j = mi % 3;
            src = (j == 0) ? convW2 + (size_t)l * 16384
                : (j == 1) ? linW + (size_t)l * 16384
                           : convW1 + (size_t)(l + 1) * 16384;
        }
        __half* dst = g_wt + (size_t)mi * WSLOT;
        for (int idx = tid; idx < 16384; idx += 512) {
            int k = idx >> 7, n = idx & 127;
            dst[k * PH + n] = __float2half(src[idx]);
        }
    } else if (b < 20) {
        int halfsel = b - 18;
        for (int i = tid; i < 16384; i += 512) {
            int idx = halfsel * 16384 + i;
            int k = idx >> 7, n = idx & 127;
            g_wc[k * PH + n] = __float2half(ncombW[idx]);
        }
    } else if (b < 220) {
        for (int idx = (b - 20) * 512 + tid; idx < NA * HD; idx += 200 * 512) {
            int i = idx >> 7, h = idx & 127;
            int zz = z[i];
            g_x[idx] = emb[(size_t)zz * HD + h];
            g_yh[idx] = __float2half(nemb[(size_t)zz * HD + h]);
        }
    } else {
        int e = (b - 220) * 512 + tid;
        if (e >= NE) return;
        int s = ei[e], d = ei[NE + e];
        float dx = pos[3 * s + 0] - pos[3 * d + 0];
        float dy = pos[3 * s + 1] - pos[3 * d + 1];
        float dz = pos[3 * s + 2] - pos[3 * d + 2];
        float d2 = dx * dx + dy * dy + dz * dz + 1e-12f;
        if (d2 < CUTR * CUTR) {
            float u = expf(-sqrtf(d2));
            int slot = atomicAdd(&g_cnt[d], 1);
            if (slot < BKT)
                g_bkt[(size_t)d * BKT + slot] = make_int2(s, __float_as_int(u));
        }
    }
}

// ---------------- scatter v3: warp/node, half-warp/edge (proven best) ----------------
__device__ __forceinline__ void edge_acc16(int j, int n, int hl, int self_mask,
        const __half* __restrict__ TBL, const __half* __restrict__ Y, float* acc) {
    int2 ed = __ldg(&g_bkt[j]);
    int s = ed.x;
    float u = __int_as_float(ed.y);
    float tf = fminf(fmaxf((u - UMINF) * SCALEF, 0.f), (float)(NT - 1));
    int ti = (int)tf;
    if (ti > NT - 2) ti = NT - 2;
    float fr = tf - (float)ti;
    float g = (self_mask && (s == n)) ? 0.f : 1.f;
    const uint4* r0 = (const uint4*)TBL + (size_t)ti * 16 + hl;
    uint4 h0 = __ldg(r0);
    uint4 h1 = __ldg(r0 + 16);
    uint4 hy = __ldg((const uint4*)Y + (size_t)s * 16 + hl);
    __half2 fr2 = __float2half2_rn(fr);
    unsigned A[4] = {h0.x, h0.y, h0.z, h0.w};
    unsigned B[4] = {h1.x, h1.y, h1.z, h1.w};
    unsigned Yv[4] = {hy.x, hy.y, hy.z, hy.w};
    #pragma unroll
    for (int q = 0; q < 4; q++) {
        __half2 a2 = *(__half2*)&A[q];
        __half2 b2 = *(__half2*)&B[q];
        __half2 y2 = *(__half2*)&Yv[q];
        __half2 w = __hfma2(fr2, __hsub2(b2, a2), a2);
        __half2 p = __hmul2(w, y2);
        float2 f = __half22float2(p);
        acc[2 * q]     = fmaf(f.x, g, acc[2 * q]);
        acc[2 * q + 1] = fmaf(f.y, g, acc[2 * q + 1]);
    }
}

__global__ __launch_bounds__(256)
void scatter_kernel(const __half* __restrict__ TBL, const __half* __restrict__ Y,
                    __half* __restrict__ M, int self_mask) {
    int warp = threadIdx.x >> 5, lane = threadIdx.x & 31;
    int hw = lane >> 4, hl = lane & 15;
    int n = blockIdx.x * 8 + warp;
    if (n >= NA) return;
    int cnt = min(__ldg(&g_cnt[n]), BKT);
    int beg = n * BKT, end = beg + cnt;
    float a0[8] = {0.f, 0.f, 0.f, 0.f, 0.f, 0.f, 0.f, 0.f};
    float a1[8] = {0.f, 0.f, 0.f, 0.f, 0.f, 0.f, 0.f, 0.f};
    int j = beg + hw;
    for (; j + 2 < end; j += 4) {
        edge_acc16(j, n, hl, self_mask, TBL, Y, a0);
        edge_acc16(j + 2, n, hl, self_mask, TBL, Y, a1);
    }
    if (j < end) edge_acc16(j, n, hl, self_mask, TBL, Y, a0);
    #pragma unroll
    for (int q = 0; q < 8; q++) a0[q] += a1[q];
    #pragma unroll
    for (int q = 0; q < 8; q++) a0[q] += __shfl_xor_sync(0xffffffffu, a0[q], 16);
    if (hw == 0) {
        __half2 h[4];
        #pragma unroll
        for (int q = 0; q < 4; q++) h[q] = __floats2half2_rn(a0[2 * q], a0[2 * q + 1]);
        uint4 st;
        st.x = *(unsigned*)&h[0]; st.y = *(unsigned*)&h[1];
        st.z = *(unsigned*)&h[2]; st.w = *(unsigned*)&h[3];
        ((uint4*)(M + (size_t)n * HD))[hl] = st;
    }
}

// ================= mma.sync building blocks =================
__device__ __forceinline__ void mma_gemm(uint32_t aBase, int ksteps, uint32_t wBase, float* c) {
    #pragma unroll 2
    for (int k = 0; k < ksteps; k++) {
        uint32_t a0, a1, a2, a3;
        asm volatile("ldmatrix.sync.aligned.m8n8.x4.shared.b16 {%0,%1,%2,%3}, [%4];"
            : "=r"(a0), "=r"(a1), "=r"(a2), "=r"(a3) : "r"(aBase + k * 32));
        #pragma unroll
        for (int nbp = 0; nbp < 8; nbp++) {
            uint32_t b0, b1, b2r, b3;
            asm volatile("ldmatrix.sync.aligned.m8n8.x4.trans.shared.b16 {%0,%1,%2,%3}, [%4];"
                : "=r"(b0), "=r"(b1), "=r"(b2r), "=r"(b3)
                : "r"(wBase + k * (16 * 272) + nbp * 32));
            float* cp = c + nbp * 8;
            asm volatile("mma.sync.aligned.m16n8k16.row.col.f32.f16.f16.f32 "
                "{%0,%1,%2,%3}, {%4,%5,%6,%7}, {%8,%9}, {%0,%1,%2,%3};"
                : "+f"(cp[0]), "+f"(cp[1]), "+f"(cp[2]), "+f"(cp[3])
                : "r"(a0), "r"(a1), "r"(a2), "r"(a3), "r"(b0), "r"(b1));
            asm volatile("mma.sync.aligned.m16n8k16.row.col.f32.f16.f16.f32 "
                "{%0,%1,%2,%3}, {%4,%5,%6,%7}, {%8,%9}, {%0,%1,%2,%3};"
                : "+f"(cp[4]), "+f"(cp[5]), "+f"(cp[6]), "+f"(cp[7])
                : "r"(a0), "r"(a1), "r"(a2), "r"(a3), "r"(b2r), "r"(b3));
        }
    }
}

// ================= fused3 via mma.sync (TM=80, 160 thr, grid 125) =================
__global__ __launch_bounds__(MTHR, 1)
void fused3_mma(const __half* __restrict__ M, const __half* __restrict__ WT,
                const float* __restrict__ b2, const float* __restrict__ bL,
                const float* __restrict__ X,
                float* __restrict__ xout, __half* __restrict__ yout, int has3) {
    extern __shared__ char smc[];
    uint32_t sb = smem_u32(smc);
    float* sBias = (float*)(smc + 126208);
    int tid = threadIdx.x, lane = tid & 31, warp = tid >> 5;
    int nw = has3 ? 3 : 2;
    {
        const uint4* ws = (const uint4*)WT;
        uint4* wd = (uint4*)(smc + 21760);
        for (int i = tid; i < nw * 2176; i += MTHR) wd[i] = ws[i];
    }
    if (tid < 128) { sBias[tid] = b2[tid]; sBias[128 + tid] = bL[tid]; }
    {
        int row = tid >> 1, sel = tid & 1;
        int node = min(blockIdx.x * TM + row, NA - 1);
        const uint4* src = (const uint4*)(M + (size_t)node * HD) + sel * 8;
        uint4* dst = (uint4*)(smc + row * 272 + sel * 128);
        #pragma unroll
        for (int i = 0; i < 8; i++) dst[i] = __ldg(src + i);
    }
    __syncthreads();

    int r0 = warp * 16;
    uint32_t aBase = sb + (r0 + (lane & 15)) * 272 + (lane >> 4) * 16;
    uint32_t bOff = ((lane & 7) + ((lane >> 3) & 1) * 8) * 272 + (lane >> 4) * 16;
    int cx = (lane & 3) * 2;
    int rtl = r0 + (lane >> 2);
    int nodeT = blockIdx.x * TM + rtl;
    int nodeB = nodeT + 8;
    int nT = min(nodeT, NA - 1), nB = min(nodeB, NA - 1);
    float c[64];

    #pragma unroll
    for (int nb = 0; nb < 16; nb++) {
        float bx0 = sBias[nb * 8 + cx], bx1 = sBias[nb * 8 + cx + 1];
        c[nb * 4 + 0] = bx0; c[nb * 4 + 1] = bx1; c[nb * 4 + 2] = bx0; c[nb * 4 + 3] = bx1;
    }
    mma_gemm(aBase, 8, sb + 21760 + bOff, c);
    __syncwarp();
    #pragma unroll
    for (int nb = 0; nb < 16; nb++) {
        int col = nb * 8 + cx;
        *(__half2*)(smc + rtl * 272 + col * 2) =
            __floats2half2_rn(silu_f(c[nb * 4 + 0]), silu_f(c[nb * 4 + 1]));
        *(__half2*)(smc + (rtl + 8) * 272 + col * 2) =
            __floats2half2_rn(silu_f(c[nb * 4 + 2]), silu_f(c[nb * 4 + 3]));
    }
    __syncwarp();

    #pragma unroll
    for (int nb = 0; nb < 16; nb++) {
        float bx0 = sBias[128 + nb * 8 + cx], bx1 = sBias[128 + nb * 8 + cx + 1];
        c[nb * 4 + 0] = bx0; c[nb * 4 + 1] = bx1; c[nb * 4 + 2] = bx0; c[nb * 4 + 3] = bx1;
    }
    mma_gemm(aBase, 8, sb + 21760 + 34816 + bOff, c);
    __syncwarp();
    #pragma unroll
    for (int nb = 0; nb < 16; nb++) {
        int col = nb * 8 + cx;
        float2 xT = *(const float2*)(X + (size_t)nT * HD + col);
        float2 xB = *(const float2*)(X + (size_t)nB * HD + col);
        float vT0 = c[nb * 4 + 0] + xT.x, vT1 = c[nb * 4 + 1] + xT.y;
        float vB0 = c[nb * 4 + 2] + xB.x, vB1 = c[nb * 4 + 3] + xB.y;
        if (nodeT < NA) *(float2*)(xout + (size_t)nodeT * HD + col) = make_float2(vT0, vT1);
        if (nodeB < NA) *(float2*)(xout + (size_t)nodeB * HD + col) = make_float2(vB0, vB1);
        if (has3) {
            *(__half2*)(smc + rtl * 272 + col * 2) = __floats2half2_rn(vT0, vT1);
            *(__half2*)(smc + (rtl + 8) * 272 + col * 2) = __floats2half2_rn(vB0, vB1);
        }
    }
    if (!has3) return;
    __syncwarp();

    #pragma unroll
    for (int i = 0; i < 64; i++) c[i] = 0.f;
    mma_gemm(aBase, 8, sb + 21760 + 69632 + bOff, c);
    #pragma unroll
    for (int nb = 0; nb < 16; nb++) {
        int col = nb * 8 + cx;
        if (nodeT < NA)
            *(__half2*)(yout + (size_t)nodeT * HD + col) =
                __floats2half2_rn(c[nb * 4 + 0], c[nb * 4 + 1]);
        if (nodeB < NA)
            *(__half2*)(yout + (size_t)nodeB * HD + col) =
                __floats2half2_rn(c[nb * 4 + 2], c[nb * 4 + 3]);
    }
}

// ================= comb via mma.sync (TM=80, 160 thr, grid 125) =================
__global__ __launch_bounds__(MTHR, 1)
void comb_mma(const __half* __restrict__ Wc, const __half* __restrict__ W1,
              const float* __restrict__ bc) {
    extern __shared__ char smc[];
    uint32_t sb = smem_u32(smc);
    float* sBias = (float*)(smc + 146688);
    int tid = threadIdx.x, lane = tid & 31, warp = tid >> 5;
    {
        const uint4* ws = (const uint4*)Wc;
        uint4* wd = (uint4*)(smc + 42240);
        for (int i = tid; i < 4352; i += MTHR) wd[i] = ws[i];
        const uint4* w1s = (const uint4*)W1;
        uint4* w1d = (uint4*)(smc + 111872);
        for (int i = tid; i < 2176; i += MTHR) w1d[i] = w1s[i];
    }
    if (tid < 128) sBias[tid] = bc[tid];
    {
        int row = tid >> 1, sel = tid & 1;
        int node = min(blockIdx.x * TM + row, NA - 1);
        uint4* dst = (uint4*)(smc + row * 528 + sel * 256);
        if (sel == 0) {
            const float4* src = (const float4*)(g_x + (size_t)node * HD);
            #pragma unroll
            for (int i = 0; i < 16; i++) {
                float4 v0 = __ldg(src + 2 * i), v1 = __ldg(src + 2 * i + 1);
                __half2 h0 = __floats2half2_rn(v0.x, v0.y);
                __half2 h1 = __floats2half2_rn(v0.z, v0.w);
                __half2 h2 = __floats2half2_rn(v1.x, v1.y);
                __half2 h3 = __floats2half2_rn(v1.z, v1.w);
                uint4 st;
                st.x = *(unsigned*)&h0; st.y = *(unsigned*)&h1;
                st.z = *(unsigned*)&h2; st.w = *(unsigned*)&h3;
                dst[i] = st;
            }
        } else {
            const uint4* src = (const uint4*)(g_msgh + (size_t)node * HD);
            #pragma unroll
            for (int i = 0; i < 16; i++) dst[i] = __ldg(src + i);
        }
    }
    __syncthreads();

    int r0 = warp * 16;
    uint32_t aBase = sb + (r0 + (lane & 15)) * 528 + (lane >> 4) * 16;
    uint32_t bOff = ((lane & 7) + ((lane >> 3) & 1) * 8) * 272 + (lane >> 4) * 16;
    int cx = (lane & 3) * 2;
    int rtl = r0 + (lane >> 2);
    int nodeT = blockIdx.x * TM + rtl;
    int nodeB = nodeT + 8;
    float c[64];

    #pragma unroll
    for (int nb = 0; nb < 16; nb++) {
        float bx0 = sBias[nb * 8 + cx], bx1 = sBias[nb * 8 + cx + 1];
        c[nb * 4 + 0] = bx0; c[nb * 4 + 1] = bx1; c[nb * 4 + 2] = bx0; c[nb * 4 + 3] = bx1;
    }
    mma_gemm(aBase, 16, sb + 42240 + bOff, c);
    __syncwarp();
    #pragma unroll
    for (int nb = 0; nb < 16; nb++) {
        int col = nb * 8 + cx;
        float vT0 = c[nb * 4 + 0], vT1 = c[nb * 4 + 1];
        float vB0 = c[nb * 4 + 2], vB1 = c[nb * 4 + 3];
        if (nodeT < NA) *(float2*)(g_x + (size_t)nodeT * HD + col) = make_float2(vT0, vT1);
        if (nodeB < NA) *(float2*)(g_x + (size_t)nodeB * HD + col) = make_float2(vB0, vB1);
        *(__half2*)(smc + rtl * 528 + col * 2) = __floats2half2_rn(vT0, vT1);
        *(__half2*)(smc + (rtl + 8) * 528 + col * 2) = __floats2half2_rn(vB0, vB1);
    }
    __syncwarp();

    #pragma unroll
    for (int i = 0; i < 64; i++) c[i] = 0.f;
    mma_gemm(aBase, 8, sb + 111872 + bOff, c);
    #pragma unroll
    for (int nb = 0; nb < 16; nb++) {
        int col = nb * 8 + cx;
        if (nodeT < NA)
            *(__half2*)(g_yh + (size_t)nodeT * HD + col) =
                __floats2half2_rn(c[nb * 4 + 0], c[nb * 4 + 1]);
        if (nodeB < NA)
            *(__half2*)(g_yh + (size_t)nodeB * HD + col) =
                __floats2half2_rn(c[nb * 4 + 2], c[nb * 4 + 3]);
    }
}

// ---------------- launcher ----------------
extern "C" void kernel_launch(void* const* d_in, const int* in_sizes, int n_in,
                              void* d_out, int out_size) {
    const int*   z      = (const int*)d_in[0];
    const float* pos    = (const float*)d_in[1];
    const int*   ei     = (const int*)d_in[3];
    const float* emb    = (const float*)d_in[4];
    const float* nemb   = (const float*)d_in[5];
    const float* nprojW = (const float*)d_in[6];
    const float* nprojB = (const float*)d_in[7];
    const float* ncombW = (const float*)d_in[8];
    const float* ncombB = (const float*)d_in[9];
    const float* means  = (const float*)d_in[10];
    const float* betas  = (const float*)d_in[11];
    const float* mlpW1  = (const float*)d_in[12];
    const float* mlpb1  = (const float*)d_in[13];
    const float* mlpW2  = (const float*)d_in[14];
    const float* mlpb2  = (const float*)d_in[15];
    const float* convW1 = (const float*)d_in[16];
    const float* convW2 = (const float*)d_in[17];
    const float* convb2 = (const float*)d_in[18];
    const float* linW   = (const float*)d_in[19];
    const float* linb   = (const float*)d_in[20];
    float* out = (float*)d_out;

    void *p_cnt, *p_x, *p_yh, *p_mh, *p_msgh, *p_tc, *p_tn, *p_wt, *p_wc;
    cudaGetSymbolAddress(&p_cnt, g_cnt);
    cudaGetSymbolAddress(&p_x, g_x);
    cudaGetSymbolAddress(&p_yh, g_yh);
    cudaGetSymbolAddress(&p_mh, g_mh);
    cudaGetSymbolAddress(&p_msgh, g_msgh);
    cudaGetSymbolAddress(&p_tc, g_tblcf_h);
    cudaGetSymbolAddress(&p_tn, g_tbln_h);
    cudaGetSymbolAddress(&p_wt, g_wt);
    cudaGetSymbolAddress(&p_wc, g_wc);
    float* px = (float*)p_x;
    __half* pyh = (__half*)p_yh;
    __half* pmh = (__half*)p_mh;
    __half* pmsgh = (__half*)p_msgh;
    __half* ptc = (__half*)p_tc;
    __half* ptn = (__half*)p_tn;
    __half* pwt = (__half*)p_wt;
    __half* pwc = (__half*)p_wc;

    size_t sh_heavy = (size_t)28992 * sizeof(float);
    size_t sh_f3m   = 127232;
    size_t sh_cmm   = 147200;
    cudaFuncSetAttribute(setup_heavy, cudaFuncAttributeMaxDynamicSharedMemorySize, (int)sh_heavy);
    cudaFuncSetAttribute(fused3_mma,  cudaFuncAttributeMaxDynamicSharedMemorySize, (int)sh_f3m);
    cudaFuncSetAttribute(comb_mma,    cudaFuncAttributeMaxDynamicSharedMemorySize, (int)sh_cmm);

    cudaMemsetAsync(p_cnt, 0, NA * sizeof(int));
    setup_light<<<845, 512>>>(ei, pos, z, emb, nemb, convW1, convW2, linW, ncombW);
    setup_heavy<<<128, 512, sh_heavy>>>(means, betas, nprojW, nprojB,
                                        mlpW1, mlpb1, mlpW2, mlpb2);
    scatter_kernel<<<(NA + 7) / 8, 256>>>(ptn, pyh, pmsgh, 1);
    comb_mma<<<NBLKM, MTHR, sh_cmm>>>(pwc, pwt + (size_t)17 * WSLOT, ncombB);

    for (int l = 0; l < NL; l++) {
        scatter_kernel<<<(NA + 7) / 8, 256>>>(ptc + (size_t)l * NT * HD, pyh, pmh, 0);
        float* dest = (l == NL - 1) ? out : px;
        fused3_mma<<<NBLKM, MTHR, sh_f3m>>>(pmh, pwt + (size_t)(l * 3) * WSLOT,
                                            convb2 + (size_t)l * HD,
                                            linb + (size_t)l * HD,
                                            px, dest, pyh, (l < NL - 1) ? 1 : 0);
    }
}